// round 10
// baseline (speedup 1.0000x reference)
#include <cuda_runtime.h>
#include <cuda_fp16.h>
#include <mma.h>
#include <cfloat>

using namespace nvcuda;

#define NN   50000
#define EE   800000
#define ECAP 64        // real-edge capacity (Poisson(16); P(deg>63) ~ 1e-18)
#define EC2  66        // + self-loop slot + zero pad slot
#define NEG_SLOPE 0.2f
#define BN_EPS 1e-5f
#define LDA 136

// ---------------- scratch (device globals) ----------------
__device__ int g_cnt[NN];
__device__ __align__(16) int2 g_ew[(size_t)NN * EC2];  // {src, half2 weights}
__device__ __align__(16) __half g_h1h [NN * 128];
__device__ float g_al1s[NN * 2];
__device__ float g_al1d[NN * 2];
__device__ __align__(16) __half g_out1h[NN * 128];
__device__ __align__(16) __half g_h2h [NN * 40];
__device__ float g_al2s[NN];
__device__ float g_al2d[NN];

// ---------------- helpers ----------------
__device__ __forceinline__ float lrelu(float x) { return x > 0.f ? x : NEG_SLOPE * x; }
__device__ __forceinline__ float warpSum(float v) {
    #pragma unroll
    for (int o = 16; o; o >>= 1) v += __shfl_xor_sync(0xffffffffu, v, o);
    return v;
}
__device__ __forceinline__ float warpMax(float v) {
    #pragma unroll
    for (int o = 16; o; o >>= 1) v = fmaxf(v, __shfl_xor_sync(0xffffffffu, v, o));
    return v;
}

// ================= K1: scatter real edges (cnt zeroed by memset) =================
__global__ void k_scatter(const int* __restrict__ ei) {
    int t = blockIdx.x * blockDim.x + threadIdx.x;
    if (t >= EE / 4) return;
    int4 s4 = *(const int4*)(ei + t * 4);
    int4 d4 = *(const int4*)(ei + EE + t * 4);
    int p;
    p = atomicAdd(&g_cnt[d4.x], 1); g_ew[(size_t)d4.x * EC2 + p].x = s4.x;
    p = atomicAdd(&g_cnt[d4.y], 1); g_ew[(size_t)d4.y * EC2 + p].x = s4.y;
    p = atomicAdd(&g_cnt[d4.z], 1); g_ew[(size_t)d4.z * EC2 + p].x = s4.z;
    p = atomicAdd(&g_cnt[d4.w], 1); g_ew[(size_t)d4.w * EC2 + p].x = s4.w;
}

// ================= K2: GEMM1 wmma fp16, 64-row tiles =================
__global__ __launch_bounds__(256) void k_gemm1(const float* __restrict__ X,
                                               const float* __restrict__ W,
                                               const float* __restrict__ a1s,
                                               const float* __restrict__ a1d) {
    extern __shared__ __align__(16) __half dyn[];
    __half* sA = dyn;                  // 64 x LDA
    __half* sW = dyn + 64 * LDA;       // 128 x LDA
    __shared__ float sAs[128], sAd[128];

    const int tid = threadIdx.x;
    const int warp = tid >> 5, lane = tid & 31;
    const int row0 = blockIdx.x * 64;
    const int validRows = min(64, NN - row0);

    if (tid < 128) { sAs[tid] = a1s[tid]; sAd[tid] = a1d[tid]; }

    #pragma unroll
    for (int i = 0; i < 8; i++) {
        int idx = tid + i * 256;
        int r = idx >> 5, c = (idx & 31) * 4;
        float4 v = make_float4(0.f, 0.f, 0.f, 0.f);
        if (r < validRows) v = *(const float4*)(X + (size_t)(row0 + r) * 128 + c);
        __half2 h0 = __floats2half2_rn(v.x, v.y);
        __half2 h1 = __floats2half2_rn(v.z, v.w);
        uint2 st; st.x = *(unsigned*)&h0; st.y = *(unsigned*)&h1;
        *(uint2*)(sA + r * LDA + c) = st;
    }
    #pragma unroll
    for (int i = 0; i < 16; i++) {
        int idx = tid + i * 256;
        int r = idx >> 5, c = (idx & 31) * 4;
        float4 v = *(const float4*)(W + (size_t)r * 128 + c);
        __half2 h0 = __floats2half2_rn(v.x, v.y);
        __half2 h1 = __floats2half2_rn(v.z, v.w);
        uint2 st; st.x = *(unsigned*)&h0; st.y = *(unsigned*)&h1;
        *(uint2*)(sW + r * LDA + c) = st;
    }
    __syncthreads();

    const int wr = warp & 3;
    const int wc = warp >> 2;

    wmma::fragment<wmma::accumulator, 16, 16, 16, float> acc[4];
    #pragma unroll
    for (int nf = 0; nf < 4; nf++) wmma::fill_fragment(acc[nf], 0.f);
    #pragma unroll
    for (int k0 = 0; k0 < 128; k0 += 16) {
        wmma::fragment<wmma::matrix_a, 16, 16, 16, __half, wmma::row_major> af;
        wmma::load_matrix_sync(af, sA + (wr * 16) * LDA + k0, LDA);
        #pragma unroll
        for (int nf = 0; nf < 4; nf++) {
            wmma::fragment<wmma::matrix_b, 16, 16, 16, __half, wmma::row_major> bf;
            wmma::load_matrix_sync(bf, sW + k0 * LDA + wc * 64 + nf * 16, LDA);
            wmma::mma_sync(acc[nf], af, bf, acc[nf]);
        }
    }
    __syncthreads();

    float* sC = (float*)dyn + warp * 320;
    const int rloc = lane & 15;
    const int coff = (lane >> 4) * 8;
    const int gr = row0 + wr * 16 + rloc;
    float ps = 0.f, pd = 0.f;

    #pragma unroll
    for (int nf = 0; nf < 4; nf++) {
        wmma::store_matrix_sync(sC, acc[nf], 20, wmma::mem_row_major);
        __syncwarp();
        float v[8];
        #pragma unroll
        for (int j = 0; j < 8; j++) v[j] = sC[rloc * 20 + coff + j];
        int cbase = wc * 64 + nf * 16 + coff;
        #pragma unroll
        for (int j = 0; j < 8; j++) { ps += v[j] * sAs[cbase + j]; pd += v[j] * sAd[cbase + j]; }
        if (gr < NN) {
            __half2 h0 = __floats2half2_rn(v[0], v[1]);
            __half2 h1 = __floats2half2_rn(v[2], v[3]);
            __half2 h2 = __floats2half2_rn(v[4], v[5]);
            __half2 h3 = __floats2half2_rn(v[6], v[7]);
            uint4 st;
            st.x = *(unsigned*)&h0; st.y = *(unsigned*)&h1;
            st.z = *(unsigned*)&h2; st.w = *(unsigned*)&h3;
            *(uint4*)(g_h1h + (size_t)gr * 128 + cbase) = st;
        }
        __syncwarp();
    }
    ps += __shfl_xor_sync(0xffffffffu, ps, 16);
    pd += __shfl_xor_sync(0xffffffffu, pd, 16);
    if (lane < 16 && gr < NN) {
        g_al1s[2 * gr + wc] = ps;
        g_al1d[2 * gr + wc] = pd;
    }
}

// ================= K3: layer-1 edge weights (normalized, fp16, packed with src) =================
__global__ __launch_bounds__(256) void k_edgew1() {
    int d = (blockIdx.x * blockDim.x + threadIdx.x) >> 5;
    int lane = threadIdx.x & 31;
    if (d >= NN) return;
    const int deg = g_cnt[d];
    const int tot = deg + 1;                   // + self-loop
    int2* erow = g_ew + (size_t)d * EC2;
    float2 ad = *(const float2*)(g_al1d + 2 * d);

    // pass 1: denominators
    float s0 = 0.f, s1 = 0.f;
    for (int base = 0; base < tot; base += 32) {
        int i = base + lane;
        if (i < tot) {
            int src = (i < deg) ? erow[i].x : d;
            float2 as = *(const float2*)(g_al1s + 2 * src);
            s0 += __expf(lrelu(as.x + ad.x));
            s1 += __expf(lrelu(as.y + ad.y));
        }
    }
    s0 = warpSum(s0); s1 = warpSum(s1);
    float inv0 = 1.f / (s0 + 1e-16f);
    float inv1 = 1.f / (s1 + 1e-16f);

    // pass 2: write normalized weights (al1s reads are L1-hot)
    for (int base = 0; base < tot; base += 32) {
        int i = base + lane;
        if (i < tot) {
            int src = (i < deg) ? erow[i].x : d;
            float2 as = *(const float2*)(g_al1s + 2 * src);
            float w0 = __expf(lrelu(as.x + ad.x)) * inv0;
            float w1 = __expf(lrelu(as.y + ad.y)) * inv1;
            __half2 w = __floats2half2_rn(w0, w1);
            int2 st; st.x = src; st.y = *(int*)&w;
            erow[i] = st;
        }
    }
    if (lane == 0) {   // zero-weight pad for odd tot
        __half2 z = __floats2half2_rn(0.f, 0.f);
        int2 st; st.x = d; st.y = *(int*)&z;
        erow[tot] = st;
    }
}

// ================= K4: layer-1 gather — shuffle-free, pre-normalized weights =================
__global__ __launch_bounds__(256) void k_agg1(const float* __restrict__ b1,
                                              const float* __restrict__ gamma,
                                              const float* __restrict__ beta,
                                              const float* __restrict__ mean,
                                              const float* __restrict__ var) {
    int d = (blockIdx.x * blockDim.x + threadIdx.x) >> 5;
    int lane = threadIdx.x & 31;
    if (d >= NN) return;
    const int tot = g_cnt[d] + 1;
    const int pairs = (tot + 1) >> 1;
    const int2* erow = g_ew + (size_t)d * EC2;
    const int half16 = lane >> 4;
    const int l16 = lane & 15;
    const bool head1 = (l16 >= 8);

    __half2 haccA[4], haccB[4];
    #pragma unroll
    for (int k = 0; k < 4; k++) {
        haccA[k] = __floats2half2_rn(0.f, 0.f);
        haccB[k] = __floats2half2_rn(0.f, 0.f);
    }

    int j = 0;
    for (; j + 2 <= pairs; j += 2) {
        int2 ewA = erow[2 * j + half16];
        int2 ewB = erow[2 * j + 2 + half16];
        uint4 rA = *(const uint4*)(g_h1h + (size_t)ewA.x * 128 + l16 * 8);
        uint4 rB = *(const uint4*)(g_h1h + (size_t)ewB.x * 128 + l16 * 8);
        __half2 hA = head1 ? __high2half2(*(__half2*)&ewA.y) : __low2half2(*(__half2*)&ewA.y);
        __half2 hB = head1 ? __high2half2(*(__half2*)&ewB.y) : __low2half2(*(__half2*)&ewB.y);
        haccA[0] = __hfma2(*(__half2*)&rA.x, hA, haccA[0]);
        haccA[1] = __hfma2(*(__half2*)&rA.y, hA, haccA[1]);
        haccA[2] = __hfma2(*(__half2*)&rA.z, hA, haccA[2]);
        haccA[3] = __hfma2(*(__half2*)&rA.w, hA, haccA[3]);
        haccB[0] = __hfma2(*(__half2*)&rB.x, hB, haccB[0]);
        haccB[1] = __hfma2(*(__half2*)&rB.y, hB, haccB[1]);
        haccB[2] = __hfma2(*(__half2*)&rB.z, hB, haccB[2]);
        haccB[3] = __hfma2(*(__half2*)&rB.w, hB, haccB[3]);
    }
    if (j < pairs) {
        int2 ew = erow[2 * j + half16];
        uint4 r = *(const uint4*)(g_h1h + (size_t)ew.x * 128 + l16 * 8);
        __half2 hw = head1 ? __high2half2(*(__half2*)&ew.y) : __low2half2(*(__half2*)&ew.y);
        haccA[0] = __hfma2(*(__half2*)&r.x, hw, haccA[0]);
        haccA[1] = __hfma2(*(__half2*)&r.y, hw, haccA[1]);
        haccA[2] = __hfma2(*(__half2*)&r.z, hw, haccA[2]);
        haccA[3] = __hfma2(*(__half2*)&r.w, hw, haccA[3]);
    }

    float facc[8];
    #pragma unroll
    for (int k = 0; k < 4; k++) {
        float2 fa = __half22float2(haccA[k]);
        float2 fb = __half22float2(haccB[k]);
        facc[2 * k]     = fa.x + fb.x;
        facc[2 * k + 1] = fa.y + fb.y;
    }
    #pragma unroll
    for (int k = 0; k < 8; k++) facc[k] += __shfl_xor_sync(0xffffffffu, facc[k], 16);

    if (lane < 16) {
        int c0 = l16 * 8;
        float o[8];
        #pragma unroll
        for (int h = 0; h < 2; h++) {
            int c = c0 + h * 4;
            float4 bv = *(const float4*)(b1 + c);
            float4 gm = *(const float4*)(gamma + c);
            float4 bt = *(const float4*)(beta + c);
            float4 mn = *(const float4*)(mean + c);
            float4 vr = *(const float4*)(var + c);
            o[h*4+0] = fmaxf((facc[h*4+0] + bv.x - mn.x) * rsqrtf(vr.x + BN_EPS) * gm.x + bt.x, 0.f);
            o[h*4+1] = fmaxf((facc[h*4+1] + bv.y - mn.y) * rsqrtf(vr.y + BN_EPS) * gm.y + bt.y, 0.f);
            o[h*4+2] = fmaxf((facc[h*4+2] + bv.z - mn.z) * rsqrtf(vr.z + BN_EPS) * gm.z + bt.z, 0.f);
            o[h*4+3] = fmaxf((facc[h*4+3] + bv.w - mn.w) * rsqrtf(vr.w + BN_EPS) * gm.w + bt.w, 0.f);
        }
        __half2 p0 = __floats2half2_rn(o[0], o[1]);
        __half2 p1 = __floats2half2_rn(o[2], o[3]);
        __half2 p2 = __floats2half2_rn(o[4], o[5]);
        __half2 p3 = __floats2half2_rn(o[6], o[7]);
        uint4 st;
        st.x = *(unsigned*)&p0; st.y = *(unsigned*)&p1;
        st.z = *(unsigned*)&p2; st.w = *(unsigned*)&p3;
        *(uint4*)(g_out1h + (size_t)d * 128 + c0) = st;
    }
}

// ================= K5: GEMM2 wmma fp16, 64-row tiles, 128 threads =================
__global__ __launch_bounds__(128) void k_gemm2(const float* __restrict__ W2,
                                               const float* __restrict__ a2s,
                                               const float* __restrict__ a2d) {
    __shared__ __align__(16) __half sA[64 * 128];
    __shared__ __align__(16) __half sB[128 * 48];
    __shared__ float sAs[48], sAd[48];

    const int tid = threadIdx.x;
    const int warp = tid >> 5, lane = tid & 31;
    const int row0 = blockIdx.x * 64;

    if (tid < 48) {
        sAs[tid] = (tid < 40) ? a2s[tid] : 0.f;
        sAd[tid] = (tid < 40) ? a2d[tid] : 0.f;
    }
    for (int idx = tid; idx < 128 * 48; idx += 128) {
        int r = idx / 48, c = idx % 48;
        sB[idx] = __float2half(c < 40 ? W2[r * 40 + c] : 0.f);
    }
    {
        const int validRows = min(64, NN - row0);
        #pragma unroll
        for (int i = 0; i < 8; i++) {
            int v4 = tid + i * 128;
            int r = v4 >> 4;
            uint4 val = make_uint4(0, 0, 0, 0);
            if (r < validRows)
                val = *(const uint4*)(g_out1h + (size_t)(row0 + r) * 128 + (v4 & 15) * 8);
            *(uint4*)(sA + v4 * 8) = val;
        }
    }
    __syncthreads();

    wmma::fragment<wmma::accumulator, 16, 16, 16, float> acc[3];
    #pragma unroll
    for (int nf = 0; nf < 3; nf++) wmma::fill_fragment(acc[nf], 0.f);
    #pragma unroll
    for (int k0 = 0; k0 < 128; k0 += 16) {
        wmma::fragment<wmma::matrix_a, 16, 16, 16, __half, wmma::row_major> af;
        wmma::load_matrix_sync(af, sA + (warp * 16) * 128 + k0, 128);
        #pragma unroll
        for (int nf = 0; nf < 3; nf++) {
            wmma::fragment<wmma::matrix_b, 16, 16, 16, __half, wmma::row_major> bf;
            wmma::load_matrix_sync(bf, sB + k0 * 48 + nf * 16, 48);
            wmma::mma_sync(acc[nf], af, bf, acc[nf]);
        }
    }
    __syncthreads();

    float* sC = (float*)sA + warp * 320;
    const int rloc = lane & 15;
    const int coff = (lane >> 4) * 8;
    const int gr = row0 + warp * 16 + rloc;
    float ps = 0.f, pd = 0.f;

    #pragma unroll
    for (int nf = 0; nf < 3; nf++) {
        wmma::store_matrix_sync(sC, acc[nf], 20, wmma::mem_row_major);
        __syncwarp();
        float v[8];
        #pragma unroll
        for (int j = 0; j < 8; j++) v[j] = sC[rloc * 20 + coff + j];
        int cbase = nf * 16 + coff;
        #pragma unroll
        for (int j = 0; j < 8; j++) { ps += v[j] * sAs[cbase + j]; pd += v[j] * sAd[cbase + j]; }
        if (gr < NN && cbase < 40) {
            __half2 h0 = __floats2half2_rn(v[0], v[1]);
            __half2 h1 = __floats2half2_rn(v[2], v[3]);
            __half2 h2 = __floats2half2_rn(v[4], v[5]);
            __half2 h3 = __floats2half2_rn(v[6], v[7]);
            uint4 st;
            st.x = *(unsigned*)&h0; st.y = *(unsigned*)&h1;
            st.z = *(unsigned*)&h2; st.w = *(unsigned*)&h3;
            *(uint4*)(g_h2h + (size_t)gr * 40 + cbase) = st;
        }
        __syncwarp();
    }
    ps += __shfl_xor_sync(0xffffffffu, ps, 16);
    pd += __shfl_xor_sync(0xffffffffu, pd, 16);
    if (lane < 16 && gr < NN) { g_al2s[gr] = ps; g_al2d[gr] = pd; }
}

// ================= K6: layer-2 edge weights (overwrite .y with normalized splat) =================
__global__ __launch_bounds__(256) void k_edgew2() {
    int d = (blockIdx.x * blockDim.x + threadIdx.x) >> 5;
    int lane = threadIdx.x & 31;
    if (d >= NN) return;
    const int tot = g_cnt[d] + 1;
    int2* erow = g_ew + (size_t)d * EC2;
    float ad = g_al2d[d];

    float s = 0.f;
    for (int base = 0; base < tot; base += 32) {
        int i = base + lane;
        if (i < tot) s += __expf(lrelu(g_al2s[erow[i].x] + ad));
    }
    s = warpSum(s);
    float inv = 1.f / (s + 1e-16f);

    for (int base = 0; base < tot; base += 32) {
        int i = base + lane;
        if (i < tot) {
            float w = __expf(lrelu(g_al2s[erow[i].x] + ad)) * inv;
            __half2 hw = __float2half2_rn(w);
            erow[i].y = *(int*)&hw;
        }
    }
    // pad slot tot keeps zero weight from k_edgew1
}

// ================= K7: layer-2 gather + log_softmax =================
__global__ __launch_bounds__(256) void k_agg2(float* __restrict__ dout,
                                              const float* __restrict__ b2) {
    int d = (blockIdx.x * blockDim.x + threadIdx.x) >> 5;
    int lane = threadIdx.x & 31;
    if (d >= NN) return;
    const int tot = g_cnt[d] + 1;
    const int pairs = (tot + 1) >> 1;
    const int2* erow = g_ew + (size_t)d * EC2;
    const int half16 = lane >> 4;
    const int l16 = lane & 15;

    __half2 haccA[2], haccB[2];
    haccA[0] = haccA[1] = __floats2half2_rn(0.f, 0.f);
    haccB[0] = haccB[1] = __floats2half2_rn(0.f, 0.f);

    int j = 0;
    for (; j + 2 <= pairs; j += 2) {
        int2 ewA = erow[2 * j + half16];
        int2 ewB = erow[2 * j + 2 + half16];
        if (l16 < 10) {
            uint2 rA = *(const uint2*)(g_h2h + (size_t)ewA.x * 40 + l16 * 4);
            uint2 rB = *(const uint2*)(g_h2h + (size_t)ewB.x * 40 + l16 * 4);
            __half2 hA = *(__half2*)&ewA.y;
            __half2 hB = *(__half2*)&ewB.y;
            haccA[0] = __hfma2(*(__half2*)&rA.x, hA, haccA[0]);
            haccA[1] = __hfma2(*(__half2*)&rA.y, hA, haccA[1]);
            haccB[0] = __hfma2(*(__half2*)&rB.x, hB, haccB[0]);
            haccB[1] = __hfma2(*(__half2*)&rB.y, hB, haccB[1]);
        }
    }
    if (j < pairs) {
        int2 ew = erow[2 * j + half16];
        if (l16 < 10) {
            uint2 r = *(const uint2*)(g_h2h + (size_t)ew.x * 40 + l16 * 4);
            __half2 hw = *(__half2*)&ew.y;
            haccA[0] = __hfma2(*(__half2*)&r.x, hw, haccA[0]);
            haccA[1] = __hfma2(*(__half2*)&r.y, hw, haccA[1]);
        }
    }

    float facc[4];
    #pragma unroll
    for (int k = 0; k < 2; k++) {
        float2 fa = __half22float2(haccA[k]);
        float2 fb = __half22float2(haccB[k]);
        facc[2 * k]     = fa.x + fb.x;
        facc[2 * k + 1] = fa.y + fb.y;
    }
    #pragma unroll
    for (int k = 0; k < 4; k++) facc[k] += __shfl_xor_sync(0xffffffffu, facc[k], 16);

    float4 o = make_float4(-FLT_MAX, -FLT_MAX, -FLT_MAX, -FLT_MAX);
    if (lane < 10) {
        float4 bv = *(const float4*)(b2 + lane * 4);
        o.x = facc[0] + bv.x;
        o.y = facc[1] + bv.y;
        o.z = facc[2] + bv.z;
        o.w = facc[3] + bv.w;
    }
    float mx = fmaxf(fmaxf(o.x, o.y), fmaxf(o.z, o.w));
    mx = warpMax(mx);
    float se = 0.f;
    if (lane < 10)
        se = __expf(o.x - mx) + __expf(o.y - mx) + __expf(o.z - mx) + __expf(o.w - mx);
    se = warpSum(se);
    float lse = __logf(se);
    if (lane < 10) {
        float4 r;
        r.x = o.x - mx - lse; r.y = o.y - mx - lse;
        r.z = o.z - mx - lse; r.w = o.w - mx - lse;
        *(float4*)(dout + (size_t)d * 40 + lane * 4) = r;
    }
}

// ================= launcher =================
extern "C" void kernel_launch(void* const* d_in, const int* in_sizes, int n_in,
                              void* d_out, int out_size) {
    const float* x   = (const float*)d_in[0];
    const int*   ei  = (const int*)  d_in[1];
    const float* W1  = (const float*)d_in[2];
    const float* a1s = (const float*)d_in[3];
    const float* a1d = (const float*)d_in[4];
    const float* b1  = (const float*)d_in[5];
    const float* bng = (const float*)d_in[6];
    const float* bnb = (const float*)d_in[7];
    const float* bnm = (const float*)d_in[8];
    const float* bnv = (const float*)d_in[9];
    const float* W2  = (const float*)d_in[10];
    const float* a2s = (const float*)d_in[11];
    const float* a2d = (const float*)d_in[12];
    const float* b2  = (const float*)d_in[13];
    float* dout = (float*)d_out;

    const int gemm1Smem = (64 + 128) * LDA * (int)sizeof(__half);  // 52224
    cudaFuncSetAttribute(k_gemm1, cudaFuncAttributeMaxDynamicSharedMemorySize, gemm1Smem);

    void* cntPtr = nullptr;
    cudaGetSymbolAddress(&cntPtr, g_cnt);
    cudaMemsetAsync(cntPtr, 0, NN * sizeof(int));

    k_scatter<<<(EE / 4 + 255) / 256, 256>>>(ei);                        // 1
    k_gemm1  <<<(NN + 63) / 64, 256, gemm1Smem>>>(x, W1, a1s, a1d);      // 2
    k_edgew1 <<<(NN * 32 + 255) / 256, 256>>>();                         // 3
    k_agg1   <<<(NN * 32 + 255) / 256, 256>>>(b1, bng, bnb, bnm, bnv);   // 4 <- profiled
    k_gemm2  <<<(NN + 63) / 64, 128>>>(W2, a2s, a2d);                    // 5
    k_edgew2 <<<(NN * 32 + 255) / 256, 256>>>();                         // 6
    k_agg2   <<<(NN * 32 + 255) / 256, 256>>>(dout, b2);                 // 7
}

// round 11
// speedup vs baseline: 1.2570x; 1.2570x over previous
#include <cuda_runtime.h>
#include <cuda_fp16.h>
#include <mma.h>
#include <cfloat>

using namespace nvcuda;

#define NN   50000
#define EE   800000
#define ECAP 64        // real-edge capacity (Poisson(16); P(deg>63) ~ 1e-18)
#define NEG_SLOPE 0.2f
#define BN_EPS 1e-5f
#define LDA 136

// ---------------- scratch (device globals) ----------------
__device__ int g_cnt[NN];
__device__ __align__(16) int g_ell[(size_t)NN * ECAP];
__device__ __align__(16) __half g_h1h [NN * 128];
__device__ float g_al1s[NN * 2];
__device__ float g_al1d[NN * 2];
__device__ __align__(16) __half g_out1h[NN * 128];
__device__ __align__(16) __half g_h2h [NN * 40];
__device__ float g_al2s[NN];
__device__ float g_al2d[NN];

// ---------------- helpers ----------------
__device__ __forceinline__ float lrelu(float x) { return x > 0.f ? x : NEG_SLOPE * x; }
__device__ __forceinline__ float warpSum(float v) {
    #pragma unroll
    for (int o = 16; o; o >>= 1) v += __shfl_xor_sync(0xffffffffu, v, o);
    return v;
}
__device__ __forceinline__ float warpMax(float v) {
    #pragma unroll
    for (int o = 16; o; o >>= 1) v = fmaxf(v, __shfl_xor_sync(0xffffffffu, v, o));
    return v;
}

// ================= K1: scatter real edges (cnt zeroed by memset) =================
__global__ void k_scatter(const int* __restrict__ ei) {
    int t = blockIdx.x * blockDim.x + threadIdx.x;
    if (t >= EE / 4) return;
    int4 s4 = *(const int4*)(ei + t * 4);
    int4 d4 = *(const int4*)(ei + EE + t * 4);
    int p;
    p = atomicAdd(&g_cnt[d4.x], 1); g_ell[(size_t)d4.x * ECAP + p] = s4.x;
    p = atomicAdd(&g_cnt[d4.y], 1); g_ell[(size_t)d4.y * ECAP + p] = s4.y;
    p = atomicAdd(&g_cnt[d4.z], 1); g_ell[(size_t)d4.z * ECAP + p] = s4.z;
    p = atomicAdd(&g_cnt[d4.w], 1); g_ell[(size_t)d4.w * ECAP + p] = s4.w;
}

// ================= K2: GEMM1 wmma fp16, 64-row tiles =================
__global__ __launch_bounds__(256) void k_gemm1(const float* __restrict__ X,
                                               const float* __restrict__ W,
                                               const float* __restrict__ a1s,
                                               const float* __restrict__ a1d) {
    extern __shared__ __align__(16) __half dyn[];
    __half* sA = dyn;                  // 64 x LDA
    __half* sW = dyn + 64 * LDA;       // 128 x LDA
    __shared__ float sAs[128], sAd[128];

    const int tid = threadIdx.x;
    const int warp = tid >> 5, lane = tid & 31;
    const int row0 = blockIdx.x * 64;
    const int validRows = min(64, NN - row0);

    if (tid < 128) { sAs[tid] = a1s[tid]; sAd[tid] = a1d[tid]; }

    #pragma unroll
    for (int i = 0; i < 8; i++) {
        int idx = tid + i * 256;
        int r = idx >> 5, c = (idx & 31) * 4;
        float4 v = make_float4(0.f, 0.f, 0.f, 0.f);
        if (r < validRows) v = *(const float4*)(X + (size_t)(row0 + r) * 128 + c);
        __half2 h0 = __floats2half2_rn(v.x, v.y);
        __half2 h1 = __floats2half2_rn(v.z, v.w);
        uint2 st; st.x = *(unsigned*)&h0; st.y = *(unsigned*)&h1;
        *(uint2*)(sA + r * LDA + c) = st;
    }
    #pragma unroll
    for (int i = 0; i < 16; i++) {
        int idx = tid + i * 256;
        int r = idx >> 5, c = (idx & 31) * 4;
        float4 v = *(const float4*)(W + (size_t)r * 128 + c);
        __half2 h0 = __floats2half2_rn(v.x, v.y);
        __half2 h1 = __floats2half2_rn(v.z, v.w);
        uint2 st; st.x = *(unsigned*)&h0; st.y = *(unsigned*)&h1;
        *(uint2*)(sW + r * LDA + c) = st;
    }
    __syncthreads();

    const int wr = warp & 3;
    const int wc = warp >> 2;

    wmma::fragment<wmma::accumulator, 16, 16, 16, float> acc[4];
    #pragma unroll
    for (int nf = 0; nf < 4; nf++) wmma::fill_fragment(acc[nf], 0.f);
    #pragma unroll
    for (int k0 = 0; k0 < 128; k0 += 16) {
        wmma::fragment<wmma::matrix_a, 16, 16, 16, __half, wmma::row_major> af;
        wmma::load_matrix_sync(af, sA + (wr * 16) * LDA + k0, LDA);
        #pragma unroll
        for (int nf = 0; nf < 4; nf++) {
            wmma::fragment<wmma::matrix_b, 16, 16, 16, __half, wmma::row_major> bf;
            wmma::load_matrix_sync(bf, sW + k0 * LDA + wc * 64 + nf * 16, LDA);
            wmma::mma_sync(acc[nf], af, bf, acc[nf]);
        }
    }
    __syncthreads();

    float* sC = (float*)dyn + warp * 320;
    const int rloc = lane & 15;
    const int coff = (lane >> 4) * 8;
    const int gr = row0 + wr * 16 + rloc;
    float ps = 0.f, pd = 0.f;

    #pragma unroll
    for (int nf = 0; nf < 4; nf++) {
        wmma::store_matrix_sync(sC, acc[nf], 20, wmma::mem_row_major);
        __syncwarp();
        float v[8];
        #pragma unroll
        for (int j = 0; j < 8; j++) v[j] = sC[rloc * 20 + coff + j];
        int cbase = wc * 64 + nf * 16 + coff;
        #pragma unroll
        for (int j = 0; j < 8; j++) { ps += v[j] * sAs[cbase + j]; pd += v[j] * sAd[cbase + j]; }
        if (gr < NN) {
            __half2 h0 = __floats2half2_rn(v[0], v[1]);
            __half2 h1 = __floats2half2_rn(v[2], v[3]);
            __half2 h2 = __floats2half2_rn(v[4], v[5]);
            __half2 h3 = __floats2half2_rn(v[6], v[7]);
            uint4 st;
            st.x = *(unsigned*)&h0; st.y = *(unsigned*)&h1;
            st.z = *(unsigned*)&h2; st.w = *(unsigned*)&h3;
            *(uint4*)(g_h1h + (size_t)gr * 128 + cbase) = st;
        }
        __syncwarp();
    }
    ps += __shfl_xor_sync(0xffffffffu, ps, 16);
    pd += __shfl_xor_sync(0xffffffffu, pd, 16);
    if (lane < 16 && gr < NN) {
        g_al1s[2 * gr + wc] = ps;
        g_al1d[2 * gr + wc] = pd;
    }
}

// ================= K3: layer-1 fused weights(smem) + gather + BN + ReLU =================
__global__ __launch_bounds__(256) void k_agg1(const float* __restrict__ b1,
                                              const float* __restrict__ gamma,
                                              const float* __restrict__ beta,
                                              const float* __restrict__ mean,
                                              const float* __restrict__ var) {
    __shared__ __align__(8) int2 sEW[8][66];
    int d = (blockIdx.x * blockDim.x + threadIdx.x) >> 5;
    int lane = threadIdx.x & 31;
    int wloc = (threadIdx.x >> 5);
    if (d >= NN) return;
    const int deg = g_cnt[d];
    const int tot = deg + 1;                   // + self-loop
    const int* ell = g_ell + (size_t)d * ECAP;
    float2 ad = *(const float2*)(g_al1d + 2 * d);

    // ---- phase 1: per-warp weight computation (one gather pass, registers) ----
    int i0 = lane, i1 = lane + 32;
    int src0 = d, src1 = d;
    float e00 = 0.f, e01 = 0.f, e10 = 0.f, e11 = 0.f;
    if (i0 < tot) {
        src0 = (i0 < deg) ? ell[i0] : d;
        float2 as = *(const float2*)(g_al1s + 2 * src0);
        e00 = __expf(lrelu(as.x + ad.x));
        e01 = __expf(lrelu(as.y + ad.y));
    }
    if (i1 < tot) {
        src1 = (i1 < deg) ? ell[i1] : d;
        float2 as = *(const float2*)(g_al1s + 2 * src1);
        e10 = __expf(lrelu(as.x + ad.x));
        e11 = __expf(lrelu(as.y + ad.y));
    }
    float s0 = warpSum(e00 + e10);
    float s1 = warpSum(e01 + e11);
    float inv0 = 1.f / (s0 + 1e-16f);
    float inv1 = 1.f / (s1 + 1e-16f);
    if (i0 < tot) {
        __half2 w = __floats2half2_rn(e00 * inv0, e01 * inv1);
        int2 st; st.x = src0; st.y = *(int*)&w;
        sEW[wloc][i0] = st;
    }
    if (i1 < tot) {
        __half2 w = __floats2half2_rn(e10 * inv0, e11 * inv1);
        int2 st; st.x = src1; st.y = *(int*)&w;
        sEW[wloc][i1] = st;
    }
    if (lane == 0) {   // zero-weight pad for odd tot
        __half2 z = __floats2half2_rn(0.f, 0.f);
        int2 st; st.x = d; st.y = *(int*)&z;
        sEW[wloc][tot] = st;
    }
    __syncwarp();

    // ---- phase 2: shuffle-free gather, 4 independent LDG.128 per iter ----
    const int pairs = (tot + 1) >> 1;
    const int half16 = lane >> 4;
    const int l16 = lane & 15;
    const bool head1 = (l16 >= 8);

    __half2 haccA[4], haccB[4];
    #pragma unroll
    for (int k = 0; k < 4; k++) {
        haccA[k] = __floats2half2_rn(0.f, 0.f);
        haccB[k] = __floats2half2_rn(0.f, 0.f);
    }

    int j = 0;
    for (; j + 4 <= pairs; j += 4) {
        int2 ew0 = sEW[wloc][2 * j + half16];
        int2 ew1 = sEW[wloc][2 * j + 2 + half16];
        int2 ew2 = sEW[wloc][2 * j + 4 + half16];
        int2 ew3 = sEW[wloc][2 * j + 6 + half16];
        uint4 r0 = *(const uint4*)(g_h1h + (size_t)ew0.x * 128 + l16 * 8);
        uint4 r1 = *(const uint4*)(g_h1h + (size_t)ew1.x * 128 + l16 * 8);
        uint4 r2 = *(const uint4*)(g_h1h + (size_t)ew2.x * 128 + l16 * 8);
        uint4 r3 = *(const uint4*)(g_h1h + (size_t)ew3.x * 128 + l16 * 8);
        __half2 h0 = head1 ? __high2half2(*(__half2*)&ew0.y) : __low2half2(*(__half2*)&ew0.y);
        __half2 h1 = head1 ? __high2half2(*(__half2*)&ew1.y) : __low2half2(*(__half2*)&ew1.y);
        __half2 h2 = head1 ? __high2half2(*(__half2*)&ew2.y) : __low2half2(*(__half2*)&ew2.y);
        __half2 h3 = head1 ? __high2half2(*(__half2*)&ew3.y) : __low2half2(*(__half2*)&ew3.y);
        haccA[0] = __hfma2(*(__half2*)&r0.x, h0, haccA[0]);
        haccA[1] = __hfma2(*(__half2*)&r0.y, h0, haccA[1]);
        haccA[2] = __hfma2(*(__half2*)&r0.z, h0, haccA[2]);
        haccA[3] = __hfma2(*(__half2*)&r0.w, h0, haccA[3]);
        haccB[0] = __hfma2(*(__half2*)&r1.x, h1, haccB[0]);
        haccB[1] = __hfma2(*(__half2*)&r1.y, h1, haccB[1]);
        haccB[2] = __hfma2(*(__half2*)&r1.z, h1, haccB[2]);
        haccB[3] = __hfma2(*(__half2*)&r1.w, h1, haccB[3]);
        haccA[0] = __hfma2(*(__half2*)&r2.x, h2, haccA[0]);
        haccA[1] = __hfma2(*(__half2*)&r2.y, h2, haccA[1]);
        haccA[2] = __hfma2(*(__half2*)&r2.z, h2, haccA[2]);
        haccA[3] = __hfma2(*(__half2*)&r2.w, h2, haccA[3]);
        haccB[0] = __hfma2(*(__half2*)&r3.x, h3, haccB[0]);
        haccB[1] = __hfma2(*(__half2*)&r3.y, h3, haccB[1]);
        haccB[2] = __hfma2(*(__half2*)&r3.z, h3, haccB[2]);
        haccB[3] = __hfma2(*(__half2*)&r3.w, h3, haccB[3]);
    }
    for (; j < pairs; j++) {
        int2 ew = sEW[wloc][2 * j + half16];
        uint4 r = *(const uint4*)(g_h1h + (size_t)ew.x * 128 + l16 * 8);
        __half2 hw = head1 ? __high2half2(*(__half2*)&ew.y) : __low2half2(*(__half2*)&ew.y);
        haccA[0] = __hfma2(*(__half2*)&r.x, hw, haccA[0]);
        haccA[1] = __hfma2(*(__half2*)&r.y, hw, haccA[1]);
        haccA[2] = __hfma2(*(__half2*)&r.z, hw, haccA[2]);
        haccA[3] = __hfma2(*(__half2*)&r.w, hw, haccA[3]);
    }

    float facc[8];
    #pragma unroll
    for (int k = 0; k < 4; k++) {
        float2 fa = __half22float2(haccA[k]);
        float2 fb = __half22float2(haccB[k]);
        facc[2 * k]     = fa.x + fb.x;
        facc[2 * k + 1] = fa.y + fb.y;
    }
    #pragma unroll
    for (int k = 0; k < 8; k++) facc[k] += __shfl_xor_sync(0xffffffffu, facc[k], 16);

    if (lane < 16) {
        int c0 = l16 * 8;
        float o[8];
        #pragma unroll
        for (int h = 0; h < 2; h++) {
            int c = c0 + h * 4;
            float4 bv = *(const float4*)(b1 + c);
            float4 gm = *(const float4*)(gamma + c);
            float4 bt = *(const float4*)(beta + c);
            float4 mn = *(const float4*)(mean + c);
            float4 vr = *(const float4*)(var + c);
            o[h*4+0] = fmaxf((facc[h*4+0] + bv.x - mn.x) * rsqrtf(vr.x + BN_EPS) * gm.x + bt.x, 0.f);
            o[h*4+1] = fmaxf((facc[h*4+1] + bv.y - mn.y) * rsqrtf(vr.y + BN_EPS) * gm.y + bt.y, 0.f);
            o[h*4+2] = fmaxf((facc[h*4+2] + bv.z - mn.z) * rsqrtf(vr.z + BN_EPS) * gm.z + bt.z, 0.f);
            o[h*4+3] = fmaxf((facc[h*4+3] + bv.w - mn.w) * rsqrtf(vr.w + BN_EPS) * gm.w + bt.w, 0.f);
        }
        __half2 p0 = __floats2half2_rn(o[0], o[1]);
        __half2 p1 = __floats2half2_rn(o[2], o[3]);
        __half2 p2 = __floats2half2_rn(o[4], o[5]);
        __half2 p3 = __floats2half2_rn(o[6], o[7]);
        uint4 st;
        st.x = *(unsigned*)&p0; st.y = *(unsigned*)&p1;
        st.z = *(unsigned*)&p2; st.w = *(unsigned*)&p3;
        *(uint4*)(g_out1h + (size_t)d * 128 + c0) = st;
    }
}

// ================= K4: GEMM2 wmma fp16, 64-row tiles, 128 threads =================
__global__ __launch_bounds__(128) void k_gemm2(const float* __restrict__ W2,
                                               const float* __restrict__ a2s,
                                               const float* __restrict__ a2d) {
    __shared__ __align__(16) __half sA[64 * 128];
    __shared__ __align__(16) __half sB[128 * 48];
    __shared__ float sAs[48], sAd[48];

    const int tid = threadIdx.x;
    const int warp = tid >> 5, lane = tid & 31;
    const int row0 = blockIdx.x * 64;

    if (tid < 48) {
        sAs[tid] = (tid < 40) ? a2s[tid] : 0.f;
        sAd[tid] = (tid < 40) ? a2d[tid] : 0.f;
    }
    for (int idx = tid; idx < 128 * 48; idx += 128) {
        int r = idx / 48, c = idx % 48;
        sB[idx] = __float2half(c < 40 ? W2[r * 40 + c] : 0.f);
    }
    {
        const int validRows = min(64, NN - row0);
        #pragma unroll
        for (int i = 0; i < 8; i++) {
            int v4 = tid + i * 128;
            int r = v4 >> 4;
            uint4 val = make_uint4(0, 0, 0, 0);
            if (r < validRows)
                val = *(const uint4*)(g_out1h + (size_t)(row0 + r) * 128 + (v4 & 15) * 8);
            *(uint4*)(sA + v4 * 8) = val;
        }
    }
    __syncthreads();

    wmma::fragment<wmma::accumulator, 16, 16, 16, float> acc[3];
    #pragma unroll
    for (int nf = 0; nf < 3; nf++) wmma::fill_fragment(acc[nf], 0.f);
    #pragma unroll
    for (int k0 = 0; k0 < 128; k0 += 16) {
        wmma::fragment<wmma::matrix_a, 16, 16, 16, __half, wmma::row_major> af;
        wmma::load_matrix_sync(af, sA + (warp * 16) * 128 + k0, 128);
        #pragma unroll
        for (int nf = 0; nf < 3; nf++) {
            wmma::fragment<wmma::matrix_b, 16, 16, 16, __half, wmma::row_major> bf;
            wmma::load_matrix_sync(bf, sB + k0 * 48 + nf * 16, 48);
            wmma::mma_sync(acc[nf], af, bf, acc[nf]);
        }
    }
    __syncthreads();

    float* sC = (float*)sA + warp * 320;
    const int rloc = lane & 15;
    const int coff = (lane >> 4) * 8;
    const int gr = row0 + warp * 16 + rloc;
    float ps = 0.f, pd = 0.f;

    #pragma unroll
    for (int nf = 0; nf < 3; nf++) {
        wmma::store_matrix_sync(sC, acc[nf], 20, wmma::mem_row_major);
        __syncwarp();
        float v[8];
        #pragma unroll
        for (int j = 0; j < 8; j++) v[j] = sC[rloc * 20 + coff + j];
        int cbase = nf * 16 + coff;
        #pragma unroll
        for (int j = 0; j < 8; j++) { ps += v[j] * sAs[cbase + j]; pd += v[j] * sAd[cbase + j]; }
        if (gr < NN && cbase < 40) {
            __half2 h0 = __floats2half2_rn(v[0], v[1]);
            __half2 h1 = __floats2half2_rn(v[2], v[3]);
            __half2 h2 = __floats2half2_rn(v[4], v[5]);
            __half2 h3 = __floats2half2_rn(v[6], v[7]);
            uint4 st;
            st.x = *(unsigned*)&h0; st.y = *(unsigned*)&h1;
            st.z = *(unsigned*)&h2; st.w = *(unsigned*)&h3;
            *(uint4*)(g_h2h + (size_t)gr * 40 + cbase) = st;
        }
        __syncwarp();
    }
    ps += __shfl_xor_sync(0xffffffffu, ps, 16);
    pd += __shfl_xor_sync(0xffffffffu, pd, 16);
    if (lane < 16 && gr < NN) { g_al2s[gr] = ps; g_al2d[gr] = pd; }
}

// ================= K5: layer-2 fused weights(smem) + gather + log_softmax =================
__global__ __launch_bounds__(256) void k_agg2(float* __restrict__ dout,
                                              const float* __restrict__ b2) {
    __shared__ __align__(8) int2 sEW[8][66];
    int d = (blockIdx.x * blockDim.x + threadIdx.x) >> 5;
    int lane = threadIdx.x & 31;
    int wloc = (threadIdx.x >> 5);
    if (d >= NN) return;
    const int deg = g_cnt[d];
    const int tot = deg + 1;
    const int* ell = g_ell + (size_t)d * ECAP;
    float ad = g_al2d[d];

    // phase 1: weights
    int i0 = lane, i1 = lane + 32;
    int src0 = d, src1 = d;
    float e0 = 0.f, e1 = 0.f;
    if (i0 < tot) {
        src0 = (i0 < deg) ? ell[i0] : d;
        e0 = __expf(lrelu(g_al2s[src0] + ad));
    }
    if (i1 < tot) {
        src1 = (i1 < deg) ? ell[i1] : d;
        e1 = __expf(lrelu(g_al2s[src1] + ad));
    }
    float s = warpSum(e0 + e1);
    float inv = 1.f / (s + 1e-16f);
    if (i0 < tot) {
        __half2 w = __float2half2_rn(e0 * inv);
        int2 st; st.x = src0; st.y = *(int*)&w;
        sEW[wloc][i0] = st;
    }
    if (i1 < tot) {
        __half2 w = __float2half2_rn(e1 * inv);
        int2 st; st.x = src1; st.y = *(int*)&w;
        sEW[wloc][i1] = st;
    }
    if (lane == 0) {
        __half2 z = __floats2half2_rn(0.f, 0.f);
        int2 st; st.x = d; st.y = *(int*)&z;
        sEW[wloc][tot] = st;
    }
    __syncwarp();

    // phase 2: gather (lanes 0..9 of each half hold the 40 cols)
    const int pairs = (tot + 1) >> 1;
    const int half16 = lane >> 4;
    const int l16 = lane & 15;

    __half2 haccA[2], haccB[2];
    haccA[0] = haccA[1] = __floats2half2_rn(0.f, 0.f);
    haccB[0] = haccB[1] = __floats2half2_rn(0.f, 0.f);

    int j = 0;
    for (; j + 2 <= pairs; j += 2) {
        int2 ewA = sEW[wloc][2 * j + half16];
        int2 ewB = sEW[wloc][2 * j + 2 + half16];
        if (l16 < 10) {
            uint2 rA = *(const uint2*)(g_h2h + (size_t)ewA.x * 40 + l16 * 4);
            uint2 rB = *(const uint2*)(g_h2h + (size_t)ewB.x * 40 + l16 * 4);
            __half2 hA = *(__half2*)&ewA.y;
            __half2 hB = *(__half2*)&ewB.y;
            haccA[0] = __hfma2(*(__half2*)&rA.x, hA, haccA[0]);
            haccA[1] = __hfma2(*(__half2*)&rA.y, hA, haccA[1]);
            haccB[0] = __hfma2(*(__half2*)&rB.x, hB, haccB[0]);
            haccB[1] = __hfma2(*(__half2*)&rB.y, hB, haccB[1]);
        }
    }
    if (j < pairs) {
        int2 ew = sEW[wloc][2 * j + half16];
        if (l16 < 10) {
            uint2 r = *(const uint2*)(g_h2h + (size_t)ew.x * 40 + l16 * 4);
            __half2 hw = *(__half2*)&ew.y;
            haccA[0] = __hfma2(*(__half2*)&r.x, hw, haccA[0]);
            haccA[1] = __hfma2(*(__half2*)&r.y, hw, haccA[1]);
        }
    }

    float facc[4];
    #pragma unroll
    for (int k = 0; k < 2; k++) {
        float2 fa = __half22float2(haccA[k]);
        float2 fb = __half22float2(haccB[k]);
        facc[2 * k]     = fa.x + fb.x;
        facc[2 * k + 1] = fa.y + fb.y;
    }
    #pragma unroll
    for (int k = 0; k < 4; k++) facc[k] += __shfl_xor_sync(0xffffffffu, facc[k], 16);

    float4 o = make_float4(-FLT_MAX, -FLT_MAX, -FLT_MAX, -FLT_MAX);
    if (lane < 10) {
        float4 bv = *(const float4*)(b2 + lane * 4);
        o.x = facc[0] + bv.x;
        o.y = facc[1] + bv.y;
        o.z = facc[2] + bv.z;
        o.w = facc[3] + bv.w;
    }
    float mx = fmaxf(fmaxf(o.x, o.y), fmaxf(o.z, o.w));
    mx = warpMax(mx);
    float se = 0.f;
    if (lane < 10)
        se = __expf(o.x - mx) + __expf(o.y - mx) + __expf(o.z - mx) + __expf(o.w - mx);
    se = warpSum(se);
    float lse = __logf(se);
    if (lane < 10) {
        float4 r;
        r.x = o.x - mx - lse; r.y = o.y - mx - lse;
        r.z = o.z - mx - lse; r.w = o.w - mx - lse;
        *(float4*)(dout + (size_t)d * 40 + lane * 4) = r;
    }
}

// ================= launcher =================
extern "C" void kernel_launch(void* const* d_in, const int* in_sizes, int n_in,
                              void* d_out, int out_size) {
    const float* x   = (const float*)d_in[0];
    const int*   ei  = (const int*)  d_in[1];
    const float* W1  = (const float*)d_in[2];
    const float* a1s = (const float*)d_in[3];
    const float* a1d = (const float*)d_in[4];
    const float* b1  = (const float*)d_in[5];
    const float* bng = (const float*)d_in[6];
    const float* bnb = (const float*)d_in[7];
    const float* bnm = (const float*)d_in[8];
    const float* bnv = (const float*)d_in[9];
    const float* W2  = (const float*)d_in[10];
    const float* a2s = (const float*)d_in[11];
    const float* a2d = (const float*)d_in[12];
    const float* b2  = (const float*)d_in[13];
    float* dout = (float*)d_out;

    const int gemm1Smem = (64 + 128) * LDA * (int)sizeof(__half);  // 52224
    cudaFuncSetAttribute(k_gemm1, cudaFuncAttributeMaxDynamicSharedMemorySize, gemm1Smem);

    void* cntPtr = nullptr;
    cudaGetSymbolAddress(&cntPtr, g_cnt);
    cudaMemsetAsync(cntPtr, 0, NN * sizeof(int));

    k_scatter<<<(EE / 4 + 255) / 256, 256>>>(ei);                        // 1
    k_gemm1  <<<(NN + 63) / 64, 256, gemm1Smem>>>(x, W1, a1s, a1d);      // 2
    k_agg1   <<<(NN * 32 + 255) / 256, 256>>>(b1, bng, bnb, bnm, bnv);   // 3
    k_gemm2  <<<(NN + 63) / 64, 128>>>(W2, a2s, a2d);                    // 4
    k_agg2   <<<(NN * 32 + 255) / 256, 256>>>(dout, b2);                 // 5
}

// round 12
// speedup vs baseline: 1.2928x; 1.0284x over previous
#include <cuda_runtime.h>
#include <cuda_fp16.h>
#include <mma.h>
#include <cfloat>

using namespace nvcuda;

#define NN   50000
#define EE   800000
#define ECAP 64        // real-edge capacity (Poisson(16); P(deg>63) ~ 1e-18)
#define NEG_SLOPE 0.2f
#define BN_EPS 1e-5f
#define LDA 136

// ---------------- scratch (device globals) ----------------
__device__ int g_cnt[NN];
__device__ __align__(16) int g_ell[(size_t)NN * ECAP];
__device__ __align__(16) __half g_h1h [NN * 128];
__device__ float g_al1s[NN * 2];
__device__ float g_al1d[NN * 2];
__device__ __align__(16) __half g_out1h[NN * 128];
__device__ __align__(16) __half g_h2h [NN * 40];
__device__ float g_al2s[NN];
__device__ float g_al2d[NN];

// ---------------- helpers ----------------
__device__ __forceinline__ float lrelu(float x) { return x > 0.f ? x : NEG_SLOPE * x; }
__device__ __forceinline__ float warpSum(float v) {
    #pragma unroll
    for (int o = 16; o; o >>= 1) v += __shfl_xor_sync(0xffffffffu, v, o);
    return v;
}
__device__ __forceinline__ float warpMax(float v) {
    #pragma unroll
    for (int o = 16; o; o >>= 1) v = fmaxf(v, __shfl_xor_sync(0xffffffffu, v, o));
    return v;
}

// ================= K1: scatter real edges (cnt zeroed by memset) =================
__global__ void k_scatter(const int* __restrict__ ei) {
    int t = blockIdx.x * blockDim.x + threadIdx.x;
    if (t >= EE / 4) return;
    int4 s4 = *(const int4*)(ei + t * 4);
    int4 d4 = *(const int4*)(ei + EE + t * 4);
    int p;
    p = atomicAdd(&g_cnt[d4.x], 1); g_ell[(size_t)d4.x * ECAP + p] = s4.x;
    p = atomicAdd(&g_cnt[d4.y], 1); g_ell[(size_t)d4.y * ECAP + p] = s4.y;
    p = atomicAdd(&g_cnt[d4.z], 1); g_ell[(size_t)d4.z * ECAP + p] = s4.z;
    p = atomicAdd(&g_cnt[d4.w], 1); g_ell[(size_t)d4.w * ECAP + p] = s4.w;
}

// ================= K2: GEMM1 wmma fp16, 64-row tiles =================
__global__ __launch_bounds__(256) void k_gemm1(const float* __restrict__ X,
                                               const float* __restrict__ W,
                                               const float* __restrict__ a1s,
                                               const float* __restrict__ a1d) {
    extern __shared__ __align__(16) __half dyn[];
    __half* sA = dyn;                  // 64 x LDA
    __half* sW = dyn + 64 * LDA;       // 128 x LDA
    __shared__ float sAs[128], sAd[128];

    const int tid = threadIdx.x;
    const int warp = tid >> 5, lane = tid & 31;
    const int row0 = blockIdx.x * 64;
    const int validRows = min(64, NN - row0);

    if (tid < 128) { sAs[tid] = a1s[tid]; sAd[tid] = a1d[tid]; }

    #pragma unroll
    for (int i = 0; i < 8; i++) {
        int idx = tid + i * 256;
        int r = idx >> 5, c = (idx & 31) * 4;
        float4 v = make_float4(0.f, 0.f, 0.f, 0.f);
        if (r < validRows) v = *(const float4*)(X + (size_t)(row0 + r) * 128 + c);
        __half2 h0 = __floats2half2_rn(v.x, v.y);
        __half2 h1 = __floats2half2_rn(v.z, v.w);
        uint2 st; st.x = *(unsigned*)&h0; st.y = *(unsigned*)&h1;
        *(uint2*)(sA + r * LDA + c) = st;
    }
    #pragma unroll
    for (int i = 0; i < 16; i++) {
        int idx = tid + i * 256;
        int r = idx >> 5, c = (idx & 31) * 4;
        float4 v = *(const float4*)(W + (size_t)r * 128 + c);
        __half2 h0 = __floats2half2_rn(v.x, v.y);
        __half2 h1 = __floats2half2_rn(v.z, v.w);
        uint2 st; st.x = *(unsigned*)&h0; st.y = *(unsigned*)&h1;
        *(uint2*)(sW + r * LDA + c) = st;
    }
    __syncthreads();

    const int wr = warp & 3;
    const int wc = warp >> 2;

    wmma::fragment<wmma::accumulator, 16, 16, 16, float> acc[4];
    #pragma unroll
    for (int nf = 0; nf < 4; nf++) wmma::fill_fragment(acc[nf], 0.f);
    #pragma unroll
    for (int k0 = 0; k0 < 128; k0 += 16) {
        wmma::fragment<wmma::matrix_a, 16, 16, 16, __half, wmma::row_major> af;
        wmma::load_matrix_sync(af, sA + (wr * 16) * LDA + k0, LDA);
        #pragma unroll
        for (int nf = 0; nf < 4; nf++) {
            wmma::fragment<wmma::matrix_b, 16, 16, 16, __half, wmma::row_major> bf;
            wmma::load_matrix_sync(bf, sW + k0 * LDA + wc * 64 + nf * 16, LDA);
            wmma::mma_sync(acc[nf], af, bf, acc[nf]);
        }
    }
    __syncthreads();

    float* sC = (float*)dyn + warp * 320;
    const int rloc = lane & 15;
    const int coff = (lane >> 4) * 8;
    const int gr = row0 + wr * 16 + rloc;
    float ps = 0.f, pd = 0.f;

    #pragma unroll
    for (int nf = 0; nf < 4; nf++) {
        wmma::store_matrix_sync(sC, acc[nf], 20, wmma::mem_row_major);
        __syncwarp();
        float v[8];
        #pragma unroll
        for (int j = 0; j < 8; j++) v[j] = sC[rloc * 20 + coff + j];
        int cbase = wc * 64 + nf * 16 + coff;
        #pragma unroll
        for (int j = 0; j < 8; j++) { ps += v[j] * sAs[cbase + j]; pd += v[j] * sAd[cbase + j]; }
        if (gr < NN) {
            __half2 h0 = __floats2half2_rn(v[0], v[1]);
            __half2 h1 = __floats2half2_rn(v[2], v[3]);
            __half2 h2 = __floats2half2_rn(v[4], v[5]);
            __half2 h3 = __floats2half2_rn(v[6], v[7]);
            uint4 st;
            st.x = *(unsigned*)&h0; st.y = *(unsigned*)&h1;
            st.z = *(unsigned*)&h2; st.w = *(unsigned*)&h3;
            *(uint4*)(g_h1h + (size_t)gr * 128 + cbase) = st;
        }
        __syncwarp();
    }
    ps += __shfl_xor_sync(0xffffffffu, ps, 16);
    pd += __shfl_xor_sync(0xffffffffu, pd, 16);
    if (lane < 16 && gr < NN) {
        g_al1s[2 * gr + wc] = ps;
        g_al1d[2 * gr + wc] = pd;
    }
}

// ================= K3: layer-1 fused weights(smem) + gather + BN + ReLU =================
__global__ __launch_bounds__(256) void k_agg1(const float* __restrict__ b1,
                                              const float* __restrict__ gamma,
                                              const float* __restrict__ beta,
                                              const float* __restrict__ mean,
                                              const float* __restrict__ var) {
    __shared__ __align__(8) int2 sEW[8][66];
    int d = (blockIdx.x * blockDim.x + threadIdx.x) >> 5;
    int lane = threadIdx.x & 31;
    int wloc = (threadIdx.x >> 5);
    if (d >= NN) return;
    const int deg = g_cnt[d];
    const int tot = deg + 1;                   // + self-loop
    const int* ell = g_ell + (size_t)d * ECAP;
    float2 ad = *(const float2*)(g_al1d + 2 * d);

    // ---- phase 1: per-warp weight computation ----
    int i0 = lane, i1 = lane + 32;
    int src0 = d, src1 = d;
    float e00 = 0.f, e01 = 0.f, e10 = 0.f, e11 = 0.f;
    if (i0 < tot) {
        src0 = (i0 < deg) ? ell[i0] : d;
        float2 as = *(const float2*)(g_al1s + 2 * src0);
        e00 = __expf(lrelu(as.x + ad.x));
        e01 = __expf(lrelu(as.y + ad.y));
    }
    if (i1 < tot) {
        src1 = (i1 < deg) ? ell[i1] : d;
        float2 as = *(const float2*)(g_al1s + 2 * src1);
        e10 = __expf(lrelu(as.x + ad.x));
        e11 = __expf(lrelu(as.y + ad.y));
    }
    float s0 = warpSum(e00 + e10);
    float s1 = warpSum(e01 + e11);
    float inv0 = 1.f / (s0 + 1e-16f);
    float inv1 = 1.f / (s1 + 1e-16f);
    if (i0 < tot) {
        __half2 w = __floats2half2_rn(e00 * inv0, e01 * inv1);
        int2 st; st.x = src0; st.y = *(int*)&w;
        sEW[wloc][i0] = st;
    }
    if (i1 < tot) {
        __half2 w = __floats2half2_rn(e10 * inv0, e11 * inv1);
        int2 st; st.x = src1; st.y = *(int*)&w;
        sEW[wloc][i1] = st;
    }
    if (lane == 0) {   // zero-weight pad for odd tot
        __half2 z = __floats2half2_rn(0.f, 0.f);
        int2 st; st.x = d; st.y = *(int*)&z;
        sEW[wloc][tot] = st;
    }
    __syncwarp();

    // ---- phase 2: shuffle-free gather, 4 independent LDG.128 per iter ----
    const int pairs = (tot + 1) >> 1;
    const int half16 = lane >> 4;
    const int l16 = lane & 15;
    const bool head1 = (l16 >= 8);

    __half2 haccA[4], haccB[4];
    #pragma unroll
    for (int k = 0; k < 4; k++) {
        haccA[k] = __floats2half2_rn(0.f, 0.f);
        haccB[k] = __floats2half2_rn(0.f, 0.f);
    }

    int j = 0;
    for (; j + 4 <= pairs; j += 4) {
        int2 ew0 = sEW[wloc][2 * j + half16];
        int2 ew1 = sEW[wloc][2 * j + 2 + half16];
        int2 ew2 = sEW[wloc][2 * j + 4 + half16];
        int2 ew3 = sEW[wloc][2 * j + 6 + half16];
        uint4 r0 = *(const uint4*)(g_h1h + (size_t)ew0.x * 128 + l16 * 8);
        uint4 r1 = *(const uint4*)(g_h1h + (size_t)ew1.x * 128 + l16 * 8);
        uint4 r2 = *(const uint4*)(g_h1h + (size_t)ew2.x * 128 + l16 * 8);
        uint4 r3 = *(const uint4*)(g_h1h + (size_t)ew3.x * 128 + l16 * 8);
        __half2 h0 = head1 ? __high2half2(*(__half2*)&ew0.y) : __low2half2(*(__half2*)&ew0.y);
        __half2 h1 = head1 ? __high2half2(*(__half2*)&ew1.y) : __low2half2(*(__half2*)&ew1.y);
        __half2 h2 = head1 ? __high2half2(*(__half2*)&ew2.y) : __low2half2(*(__half2*)&ew2.y);
        __half2 h3 = head1 ? __high2half2(*(__half2*)&ew3.y) : __low2half2(*(__half2*)&ew3.y);
        haccA[0] = __hfma2(*(__half2*)&r0.x, h0, haccA[0]);
        haccA[1] = __hfma2(*(__half2*)&r0.y, h0, haccA[1]);
        haccA[2] = __hfma2(*(__half2*)&r0.z, h0, haccA[2]);
        haccA[3] = __hfma2(*(__half2*)&r0.w, h0, haccA[3]);
        haccB[0] = __hfma2(*(__half2*)&r1.x, h1, haccB[0]);
        haccB[1] = __hfma2(*(__half2*)&r1.y, h1, haccB[1]);
        haccB[2] = __hfma2(*(__half2*)&r1.z, h1, haccB[2]);
        haccB[3] = __hfma2(*(__half2*)&r1.w, h1, haccB[3]);
        haccA[0] = __hfma2(*(__half2*)&r2.x, h2, haccA[0]);
        haccA[1] = __hfma2(*(__half2*)&r2.y, h2, haccA[1]);
        haccA[2] = __hfma2(*(__half2*)&r2.z, h2, haccA[2]);
        haccA[3] = __hfma2(*(__half2*)&r2.w, h2, haccA[3]);
        haccB[0] = __hfma2(*(__half2*)&r3.x, h3, haccB[0]);
        haccB[1] = __hfma2(*(__half2*)&r3.y, h3, haccB[1]);
        haccB[2] = __hfma2(*(__half2*)&r3.z, h3, haccB[2]);
        haccB[3] = __hfma2(*(__half2*)&r3.w, h3, haccB[3]);
    }
    for (; j < pairs; j++) {
        int2 ew = sEW[wloc][2 * j + half16];
        uint4 r = *(const uint4*)(g_h1h + (size_t)ew.x * 128 + l16 * 8);
        __half2 hw = head1 ? __high2half2(*(__half2*)&ew.y) : __low2half2(*(__half2*)&ew.y);
        haccA[0] = __hfma2(*(__half2*)&r.x, hw, haccA[0]);
        haccA[1] = __hfma2(*(__half2*)&r.y, hw, haccA[1]);
        haccA[2] = __hfma2(*(__half2*)&r.z, hw, haccA[2]);
        haccA[3] = __hfma2(*(__half2*)&r.w, hw, haccA[3]);
    }

    float facc[8];
    #pragma unroll
    for (int k = 0; k < 4; k++) {
        float2 fa = __half22float2(haccA[k]);
        float2 fb = __half22float2(haccB[k]);
        facc[2 * k]     = fa.x + fb.x;
        facc[2 * k + 1] = fa.y + fb.y;
    }
    #pragma unroll
    for (int k = 0; k < 8; k++) facc[k] += __shfl_xor_sync(0xffffffffu, facc[k], 16);

    if (lane < 16) {
        int c0 = l16 * 8;
        float o[8];
        #pragma unroll
        for (int h = 0; h < 2; h++) {
            int c = c0 + h * 4;
            float4 bv = *(const float4*)(b1 + c);
            float4 gm = *(const float4*)(gamma + c);
            float4 bt = *(const float4*)(beta + c);
            float4 mn = *(const float4*)(mean + c);
            float4 vr = *(const float4*)(var + c);
            o[h*4+0] = fmaxf((facc[h*4+0] + bv.x - mn.x) * rsqrtf(vr.x + BN_EPS) * gm.x + bt.x, 0.f);
            o[h*4+1] = fmaxf((facc[h*4+1] + bv.y - mn.y) * rsqrtf(vr.y + BN_EPS) * gm.y + bt.y, 0.f);
            o[h*4+2] = fmaxf((facc[h*4+2] + bv.z - mn.z) * rsqrtf(vr.z + BN_EPS) * gm.z + bt.z, 0.f);
            o[h*4+3] = fmaxf((facc[h*4+3] + bv.w - mn.w) * rsqrtf(vr.w + BN_EPS) * gm.w + bt.w, 0.f);
        }
        __half2 p0 = __floats2half2_rn(o[0], o[1]);
        __half2 p1 = __floats2half2_rn(o[2], o[3]);
        __half2 p2 = __floats2half2_rn(o[4], o[5]);
        __half2 p3 = __floats2half2_rn(o[6], o[7]);
        uint4 st;
        st.x = *(unsigned*)&p0; st.y = *(unsigned*)&p1;
        st.z = *(unsigned*)&p2; st.w = *(unsigned*)&p3;
        *(uint4*)(g_out1h + (size_t)d * 128 + c0) = st;
    }
}

// ================= K4: GEMM2 wmma fp16, 128-row tiles, 256 threads =================
__global__ __launch_bounds__(256) void k_gemm2(const float* __restrict__ W2,
                                               const float* __restrict__ a2s,
                                               const float* __restrict__ a2d) {
    __shared__ __align__(16) __half sA[128 * 128];   // 32 KB
    __shared__ __align__(16) __half sB[128 * 48];    // 12 KB
    __shared__ float sAs[48], sAd[48];

    const int tid = threadIdx.x;
    const int warp = tid >> 5, lane = tid & 31;
    const int row0 = blockIdx.x * 128;

    if (tid < 48) {
        sAs[tid] = (tid < 40) ? a2s[tid] : 0.f;
        sAd[tid] = (tid < 40) ? a2d[tid] : 0.f;
    }
    // W2 fill: 128x40 floats = 1280 float4, 5 per thread, vectorized
    #pragma unroll
    for (int i = 0; i < 5; i++) {
        int idx = tid + i * 256;            // 0..1279
        int r = idx / 10, c4 = idx % 10;    // row, float4-column
        float4 v = *(const float4*)(W2 + r * 40 + c4 * 4);
        __half2 h0 = __floats2half2_rn(v.x, v.y);
        __half2 h1 = __floats2half2_rn(v.z, v.w);
        uint2 st; st.x = *(unsigned*)&h0; st.y = *(unsigned*)&h1;
        *(uint2*)(sB + r * 48 + c4 * 4) = st;
    }
    // zero the pad columns 40..47
    for (int idx = tid; idx < 128; idx += 256) {
        *(uint4*)(sB + idx * 48 + 40) = make_uint4(0, 0, 0, 0);
    }
    {
        const int validRows = min(128, NN - row0);
        #pragma unroll
        for (int i = 0; i < 8; i++) {
            int v4 = tid + i * 256;            // 0..2047 uint4 (16 per row)
            int r = v4 >> 4;
            uint4 val = make_uint4(0, 0, 0, 0);
            if (r < validRows)
                val = *(const uint4*)(g_out1h + (size_t)(row0 + r) * 128 + (v4 & 15) * 8);
            *(uint4*)(sA + v4 * 8) = val;
        }
    }
    __syncthreads();

    wmma::fragment<wmma::accumulator, 16, 16, 16, float> acc[3];
    #pragma unroll
    for (int nf = 0; nf < 3; nf++) wmma::fill_fragment(acc[nf], 0.f);
    #pragma unroll
    for (int k0 = 0; k0 < 128; k0 += 16) {
        wmma::fragment<wmma::matrix_a, 16, 16, 16, __half, wmma::row_major> af;
        wmma::load_matrix_sync(af, sA + (warp * 16) * 128 + k0, 128);
        #pragma unroll
        for (int nf = 0; nf < 3; nf++) {
            wmma::fragment<wmma::matrix_b, 16, 16, 16, __half, wmma::row_major> bf;
            wmma::load_matrix_sync(bf, sB + k0 * 48 + nf * 16, 48);
            wmma::mma_sync(acc[nf], af, bf, acc[nf]);
        }
    }
    __syncthreads();

    float* sC = (float*)sA + warp * 320;
    const int rloc = lane & 15;
    const int coff = (lane >> 4) * 8;
    const int gr = row0 + warp * 16 + rloc;
    float ps = 0.f, pd = 0.f;

    #pragma unroll
    for (int nf = 0; nf < 3; nf++) {
        wmma::store_matrix_sync(sC, acc[nf], 20, wmma::mem_row_major);
        __syncwarp();
        float v[8];
        #pragma unroll
        for (int j = 0; j < 8; j++) v[j] = sC[rloc * 20 + coff + j];
        int cbase = nf * 16 + coff;
        #pragma unroll
        for (int j = 0; j < 8; j++) { ps += v[j] * sAs[cbase + j]; pd += v[j] * sAd[cbase + j]; }
        if (gr < NN && cbase < 40) {
            __half2 h0 = __floats2half2_rn(v[0], v[1]);
            __half2 h1 = __floats2half2_rn(v[2], v[3]);
            __half2 h2 = __floats2half2_rn(v[4], v[5]);
            __half2 h3 = __floats2half2_rn(v[6], v[7]);
            uint4 st;
            st.x = *(unsigned*)&h0; st.y = *(unsigned*)&h1;
            st.z = *(unsigned*)&h2; st.w = *(unsigned*)&h3;
            *(uint4*)(g_h2h + (size_t)gr * 40 + cbase) = st;
        }
        __syncwarp();
    }
    ps += __shfl_xor_sync(0xffffffffu, ps, 16);
    pd += __shfl_xor_sync(0xffffffffu, pd, 16);
    if (lane < 16 && gr < NN) { g_al2s[gr] = ps; g_al2d[gr] = pd; }
}

// ================= K5: layer-2 fused weights(smem) + gather + log_softmax =================
__global__ __launch_bounds__(256) void k_agg2(float* __restrict__ dout,
                                              const float* __restrict__ b2) {
    __shared__ __align__(8) int2 sEW[8][66];
    int d = (blockIdx.x * blockDim.x + threadIdx.x) >> 5;
    int lane = threadIdx.x & 31;
    int wloc = (threadIdx.x >> 5);
    if (d >= NN) return;
    const int deg = g_cnt[d];
    const int tot = deg + 1;
    const int* ell = g_ell + (size_t)d * ECAP;
    float ad = g_al2d[d];

    // phase 1: weights
    int i0 = lane, i1 = lane + 32;
    int src0 = d, src1 = d;
    float e0 = 0.f, e1 = 0.f;
    if (i0 < tot) {
        src0 = (i0 < deg) ? ell[i0] : d;
        e0 = __expf(lrelu(g_al2s[src0] + ad));
    }
    if (i1 < tot) {
        src1 = (i1 < deg) ? ell[i1] : d;
        e1 = __expf(lrelu(g_al2s[src1] + ad));
    }
    float s = warpSum(e0 + e1);
    float inv = 1.f / (s + 1e-16f);
    if (i0 < tot) {
        __half2 w = __float2half2_rn(e0 * inv);
        int2 st; st.x = src0; st.y = *(int*)&w;
        sEW[wloc][i0] = st;
    }
    if (i1 < tot) {
        __half2 w = __float2half2_rn(e1 * inv);
        int2 st; st.x = src1; st.y = *(int*)&w;
        sEW[wloc][i1] = st;
    }
    if (lane == 0) {
        __half2 z = __floats2half2_rn(0.f, 0.f);
        int2 st; st.x = d; st.y = *(int*)&z;
        sEW[wloc][tot] = st;
    }
    __syncwarp();

    // phase 2: gather
    const int pairs = (tot + 1) >> 1;
    const int half16 = lane >> 4;
    const int l16 = lane & 15;

    __half2 haccA[2], haccB[2];
    haccA[0] = haccA[1] = __floats2half2_rn(0.f, 0.f);
    haccB[0] = haccB[1] = __floats2half2_rn(0.f, 0.f);

    int j = 0;
    for (; j + 2 <= pairs; j += 2) {
        int2 ewA = sEW[wloc][2 * j + half16];
        int2 ewB = sEW[wloc][2 * j + 2 + half16];
        if (l16 < 10) {
            uint2 rA = *(const uint2*)(g_h2h + (size_t)ewA.x * 40 + l16 * 4);
            uint2 rB = *(const uint2*)(g_h2h + (size_t)ewB.x * 40 + l16 * 4);
            __half2 hA = *(__half2*)&ewA.y;
            __half2 hB = *(__half2*)&ewB.y;
            haccA[0] = __hfma2(*(__half2*)&rA.x, hA, haccA[0]);
            haccA[1] = __hfma2(*(__half2*)&rA.y, hA, haccA[1]);
            haccB[0] = __hfma2(*(__half2*)&rB.x, hB, haccB[0]);
            haccB[1] = __hfma2(*(__half2*)&rB.y, hB, haccB[1]);
        }
    }
    if (j < pairs) {
        int2 ew = sEW[wloc][2 * j + half16];
        if (l16 < 10) {
            uint2 r = *(const uint2*)(g_h2h + (size_t)ew.x * 40 + l16 * 4);
            __half2 hw = *(__half2*)&ew.y;
            haccA[0] = __hfma2(*(__half2*)&r.x, hw, haccA[0]);
            haccA[1] = __hfma2(*(__half2*)&r.y, hw, haccA[1]);
        }
    }

    float facc[4];
    #pragma unroll
    for (int k = 0; k < 2; k++) {
        float2 fa = __half22float2(haccA[k]);
        float2 fb = __half22float2(haccB[k]);
        facc[2 * k]     = fa.x + fb.x;
        facc[2 * k + 1] = fa.y + fb.y;
    }
    #pragma unroll
    for (int k = 0; k < 4; k++) facc[k] += __shfl_xor_sync(0xffffffffu, facc[k], 16);

    float4 o = make_float4(-FLT_MAX, -FLT_MAX, -FLT_MAX, -FLT_MAX);
    if (lane < 10) {
        float4 bv = *(const float4*)(b2 + lane * 4);
        o.x = facc[0] + bv.x;
        o.y = facc[1] + bv.y;
        o.z = facc[2] + bv.z;
        o.w = facc[3] + bv.w;
    }
    float mx = fmaxf(fmaxf(o.x, o.y), fmaxf(o.z, o.w));
    mx = warpMax(mx);
    float se = 0.f;
    if (lane < 10)
        se = __expf(o.x - mx) + __expf(o.y - mx) + __expf(o.z - mx) + __expf(o.w - mx);
    se = warpSum(se);
    float lse = __logf(se);
    if (lane < 10) {
        float4 r;
        r.x = o.x - mx - lse; r.y = o.y - mx - lse;
        r.z = o.z - mx - lse; r.w = o.w - mx - lse;
        *(float4*)(dout + (size_t)d * 40 + lane * 4) = r;
    }
}

// ================= launcher =================
extern "C" void kernel_launch(void* const* d_in, const int* in_sizes, int n_in,
                              void* d_out, int out_size) {
    const float* x   = (const float*)d_in[0];
    const int*   ei  = (const int*)  d_in[1];
    const float* W1  = (const float*)d_in[2];
    const float* a1s = (const float*)d_in[3];
    const float* a1d = (const float*)d_in[4];
    const float* b1  = (const float*)d_in[5];
    const float* bng = (const float*)d_in[6];
    const float* bnb = (const float*)d_in[7];
    const float* bnm = (const float*)d_in[8];
    const float* bnv = (const float*)d_in[9];
    const float* W2  = (const float*)d_in[10];
    const float* a2s = (const float*)d_in[11];
    const float* a2d = (const float*)d_in[12];
    const float* b2  = (const float*)d_in[13];
    float* dout = (float*)d_out;

    const int gemm1Smem = (64 + 128) * LDA * (int)sizeof(__half);  // 52224
    cudaFuncSetAttribute(k_gemm1, cudaFuncAttributeMaxDynamicSharedMemorySize, gemm1Smem);

    void* cntPtr = nullptr;
    cudaGetSymbolAddress(&cntPtr, g_cnt);
    cudaMemsetAsync(cntPtr, 0, NN * sizeof(int));

    k_scatter<<<(EE / 4 + 255) / 256, 256>>>(ei);                        // 1
    k_gemm1  <<<(NN + 63) / 64, 256, gemm1Smem>>>(x, W1, a1s, a1d);      // 2
    k_agg1   <<<(NN * 32 + 255) / 256, 256>>>(b1, bng, bnb, bnm, bnv);   // 3
    k_gemm2  <<<(NN + 127) / 128, 256>>>(W2, a2s, a2d);                  // 4 <- profiled
    k_agg2   <<<(NN * 32 + 255) / 256, 256>>>(dout, b2);                 // 5
}